// round 15
// baseline (speedup 1.0000x reference)
#include <cuda_runtime.h>
#include <cuda_bf16.h>
#include <cstdint>
#include <math.h>

#define T_SEQ 2048
#define E_DIM 1024
#define NH 8
#define LAMBDA_INIT 0.35550906759096927f

// ---------------- scratch (device globals; no runtime allocation) ----------------
__device__ float g_q[T_SEQ * E_DIM];
__device__ float g_k[T_SEQ * E_DIM];
__device__ float g_v[T_SEQ * E_DIM];
__device__ float g_lambda;
__device__ float g_rope[T_SEQ * 32 * 4];

__device__ __nv_bfloat16 g_xh[T_SEQ * E_DIM], g_xl[T_SEQ * E_DIM];
__device__ __nv_bfloat16 g_ah[T_SEQ * E_DIM], g_al[T_SEQ * E_DIM];
__device__ __nv_bfloat16 g_qbh[T_SEQ * E_DIM], g_qbl[T_SEQ * E_DIM];
__device__ __nv_bfloat16 g_kbh[T_SEQ * E_DIM], g_kbl[T_SEQ * E_DIM];
__device__ __nv_bfloat16 g_vbh[T_SEQ * E_DIM], g_vbl[T_SEQ * E_DIM];
__device__ __nv_bfloat16 g_wqh[E_DIM * E_DIM], g_wql[E_DIM * E_DIM];
__device__ __nv_bfloat16 g_wkh[E_DIM * E_DIM], g_wkl[E_DIM * E_DIM];
__device__ __nv_bfloat16 g_wvh[E_DIM * E_DIM], g_wvl[E_DIM * E_DIM];
__device__ __nv_bfloat16 g_woh[E_DIM * E_DIM], g_wol[E_DIM * E_DIM];

// ---------------- warp-MMA helpers (baseline PTX, works at sm_103 non-a) ----------------
__device__ __forceinline__ uint32_t smem_u32(const void* p) {
    uint32_t a;
    asm("{ .reg .u64 t; cvta.to.shared.u64 t, %1; cvt.u32.u64 %0, t; }" : "=r"(a) : "l"(p));
    return a;
}
__device__ __forceinline__ void ldsm4(uint32_t* r, uint32_t addr) {
    asm volatile("ldmatrix.sync.aligned.m8n8.x4.shared.b16 {%0,%1,%2,%3}, [%4];"
                 : "=r"(r[0]), "=r"(r[1]), "=r"(r[2]), "=r"(r[3]) : "r"(addr));
}
__device__ __forceinline__ void ldsm4t(uint32_t* r, uint32_t addr) {
    asm volatile("ldmatrix.sync.aligned.m8n8.x4.trans.shared.b16 {%0,%1,%2,%3}, [%4];"
                 : "=r"(r[0]), "=r"(r[1]), "=r"(r[2]), "=r"(r[3]) : "r"(addr));
}
__device__ __forceinline__ void mma16816(float* d, const uint32_t* a, const uint32_t* b) {
    asm volatile("mma.sync.aligned.m16n8k16.row.col.f32.bf16.bf16.f32 "
                 "{%0,%1,%2,%3}, {%4,%5,%6,%7}, {%8,%9}, {%0,%1,%2,%3};"
                 : "+f"(d[0]), "+f"(d[1]), "+f"(d[2]), "+f"(d[3])
                 : "r"(a[0]), "r"(a[1]), "r"(a[2]), "r"(a[3]), "r"(b[0]), "r"(b[1]));
}
__device__ __forceinline__ void cpa16(uint32_t s, const void* g) {
    asm volatile("cp.async.ca.shared.global [%0], [%1], 16;" :: "r"(s), "l"(g));
}
#define CPA_COMMIT() asm volatile("cp.async.commit_group;" ::: "memory")
#define CPA_WAIT(n)  asm volatile("cp.async.wait_group %0;" :: "n"(n) : "memory")

// ---------------- split-bf16 conversion ----------------
__global__ void cvt_split(const float* __restrict__ in, __nv_bfloat16* __restrict__ hi,
                          __nv_bfloat16* __restrict__ lo, int n) {
    int i = blockIdx.x * 256 + threadIdx.x;
    if (i < n) {
        float v = in[i];
        __nv_bfloat16 h = __float2bfloat16(v);
        hi[i] = h;
        lo[i] = __float2bfloat16(v - __bfloat162float(h));
    }
}

// fused cvt for 4 weight matrices (blockIdx.y selects)
__global__ void cvt_weights(const float* __restrict__ Wq, const float* __restrict__ Wk,
                            const float* __restrict__ Wv, const float* __restrict__ Wo,
                            __nv_bfloat16* __restrict__ qh, __nv_bfloat16* __restrict__ ql,
                            __nv_bfloat16* __restrict__ kh, __nv_bfloat16* __restrict__ kl,
                            __nv_bfloat16* __restrict__ vh, __nv_bfloat16* __restrict__ vl,
                            __nv_bfloat16* __restrict__ oh, __nv_bfloat16* __restrict__ ol) {
    int i = blockIdx.x * 256 + threadIdx.x;
    int w = blockIdx.y;
    const float* src = (w == 0) ? Wq : (w == 1) ? Wk : (w == 2) ? Wv : Wo;
    __nv_bfloat16* hi = (w == 0) ? qh : (w == 1) ? kh : (w == 2) ? vh : oh;
    __nv_bfloat16* lo = (w == 0) ? ql : (w == 1) ? kl : (w == 2) ? vl : ol;
    float v = src[i];
    __nv_bfloat16 h = __float2bfloat16(v);
    hi[i] = h;
    lo[i] = __float2bfloat16(v - __bfloat162float(h));
}

// ---------------- HMMA GEMM (cp.async double-buffered, 512 thr / 16 warps): C = A * B^T ----------------
// CTA 128x128, 16 warps (4M x 4N), warp tile 32x32, K-chunk 32. blockIdx.z selects (B, C) set.
#define GSROW 40
#define GARR 10240            /* bytes per array */
#define GBUFB 40960           /* bytes per buffer (4 arrays) */
#define GEMM_SMEM 81920

__global__ __launch_bounds__(512) void gemm_hmma(
    const __nv_bfloat16* __restrict__ Ah, const __nv_bfloat16* __restrict__ Al,
    const __nv_bfloat16* __restrict__ B0h, const __nv_bfloat16* __restrict__ B0l,
    const __nv_bfloat16* __restrict__ B1h, const __nv_bfloat16* __restrict__ B1l,
    const __nv_bfloat16* __restrict__ B2h, const __nv_bfloat16* __restrict__ B2l,
    float* __restrict__ C0, float* __restrict__ C1, float* __restrict__ C2,
    int M, int N, int K) {
    extern __shared__ char dsm[];
    const uint32_t sb = smem_u32(dsm);

    const int tid = threadIdx.x;
    const int lane = tid & 31, wid = tid >> 5;
    const int wm = wid & 3, wn = wid >> 2;       // 4 x 4 warp grid, 32x32 tiles
    const int m0 = blockIdx.y * 128, n0 = blockIdx.x * 128;
    const int z = blockIdx.z;
    const __nv_bfloat16* Bh = (z == 0) ? B0h : (z == 1) ? B1h : B2h;
    const __nv_bfloat16* Bl = (z == 0) ? B0l : (z == 1) ? B1l : B2l;
    float* C = (z == 0) ? C0 : (z == 1) ? C1 : C2;

    float acc[2][4][4];
#pragma unroll
    for (int mt = 0; mt < 2; mt++)
#pragma unroll
        for (int nt = 0; nt < 4; nt++)
#pragma unroll
            for (int i = 0; i < 4; i++) acc[mt][nt][i] = 0.f;

    // copy coords: 512 uint4 per array, 1 per thread per array
    const int rowA = tid >> 2, qA = tid & 3;
    const uint32_t soA = (uint32_t)(rowA * GSROW + qA * 8) * 2;

    const int nchunk = K >> 5;

    auto load_chunk = [&](int c, int b) {
        int k0 = c << 5;
        uint32_t bs = sb + b * GBUFB;
        size_t ga = (size_t)(m0 + rowA) * K + k0 + qA * 8;
        size_t gb = (size_t)(n0 + rowA) * K + k0 + qA * 8;
        cpa16(bs + soA, &Ah[ga]);
        cpa16(bs + GARR + soA, &Al[ga]);
        cpa16(bs + 2 * GARR + soA, &Bh[gb]);
        cpa16(bs + 3 * GARR + soA, &Bl[gb]);
        CPA_COMMIT();
    };

    load_chunk(0, 0);
    load_chunk(1, 1);

    const int quarter = lane >> 3, wi = lane & 7;

    for (int c = 0; c < nchunk; c++) {
        const int buf = c & 1;
        if (c + 1 < nchunk) CPA_WAIT(1); else CPA_WAIT(0);
        __syncthreads();

        const uint32_t uAh = sb + buf * GBUFB;
        const uint32_t uAl = uAh + GARR;
        const uint32_t uBh = uAh + 2 * GARR;
        const uint32_t uBl = uAh + 3 * GARR;

#pragma unroll
        for (int ks = 0; ks < 2; ks++) {
            uint32_t aH[2][4], aL[2][4], bH[8], bL[8];
#pragma unroll
            for (int mt = 0; mt < 2; mt++) {
                uint32_t off = (uint32_t)(wm * 32 + mt * 16 + (lane & 15)) * (GSROW * 2)
                               + ks * 32 + ((lane >> 4) * 16);
                ldsm4(aH[mt], uAh + off);
                ldsm4(aL[mt], uAl + off);
            }
#pragma unroll
            for (int p = 0; p < 2; p++) {
                uint32_t off = (uint32_t)(wn * 32 + p * 16 + (quarter >> 1) * 8 + wi) * (GSROW * 2)
                               + ks * 32 + ((quarter & 1) * 16);
                ldsm4(&bH[p * 4], uBh + off);
                ldsm4(&bL[p * 4], uBl + off);
            }
#pragma unroll
            for (int mt = 0; mt < 2; mt++)
#pragma unroll
                for (int nt = 0; nt < 4; nt++) {
                    mma16816(acc[mt][nt], aH[mt], &bH[nt * 2]);
                    mma16816(acc[mt][nt], aH[mt], &bL[nt * 2]);
                    mma16816(acc[mt][nt], aL[mt], &bH[nt * 2]);
                }
        }
        __syncthreads();
        if (c + 2 < nchunk) load_chunk(c + 2, buf);
    }

#pragma unroll
    for (int mt = 0; mt < 2; mt++) {
        int row = m0 + wm * 32 + mt * 16 + (lane >> 2);
#pragma unroll
        for (int nt = 0; nt < 4; nt++) {
            int col = n0 + wn * 32 + nt * 8 + (lane & 3) * 2;
            float2 v0 = make_float2(acc[mt][nt][0], acc[mt][nt][1]);
            float2 v1 = make_float2(acc[mt][nt][2], acc[mt][nt][3]);
            *(float2*)&C[(size_t)row * N + col] = v0;
            *(float2*)&C[(size_t)(row + 8) * N + col] = v1;
        }
    }
}

// ---------------- RoPE tables (tiny fp64 kernel) ----------------
__global__ void rope_tables(float* __restrict__ tab) {
    int t = blockIdx.x;
    int i = threadIdx.x;
    double inv = pow(10000.0, -(double)i / 32.0);
    double f = fmod((double)t * inv, 6.283185307179586);
    float cf = (float)cos(f), sf = (float)sin(f);
    float power = ((float)t - 1024.0f) / 512.0f;
    int je = (2 * i) & 31, jo = (2 * i + 1) & 31;
    float sv_e = (2.0f * je + 25.6f) / 89.6f;
    float sv_o = (2.0f * jo + 25.6f) / 89.6f;
    float se = powf(sv_e, power), so = powf(sv_o, power);
    int idx = (t * 32 + i) * 4;
    tab[idx] = cf; tab[idx + 1] = sf; tab[idx + 2] = se; tab[idx + 3] = so;
}

// ---------------- RoPE apply: fp32 in -> split bf16 out ----------------
__global__ void rope_apply(const float* __restrict__ q, const float* __restrict__ k,
                           const float* __restrict__ tab,
                           __nv_bfloat16* __restrict__ qh, __nv_bfloat16* __restrict__ ql,
                           __nv_bfloat16* __restrict__ kh, __nv_bfloat16* __restrict__ kl) {
    int t = blockIdx.x;
    int p = threadIdx.x;
    int head = p >> 5;
    int i = p & 31;
    float4 tv = *(const float4*)&tab[(t * 32 + i) * 4];
    float cf = tv.x, sf = tv.y, se = tv.z, so = tv.w;

    size_t base = (size_t)t * E_DIM + head * 64 + 2 * i;
    float a = q[base], b = q[base + 1];
    float qa = (a * cf - b * sf) * se * 0.125f;
    float qb = (b * cf + a * sf) * so * 0.125f;
    float ka = k[base], kb = k[base + 1];
    float k0 = (ka * cf - kb * sf) / se;
    float k1 = (kb * cf + ka * sf) / so;

    __nv_bfloat162 v;
    v.x = __float2bfloat16(qa); v.y = __float2bfloat16(qb);
    *(__nv_bfloat162*)&qh[base] = v;
    __nv_bfloat162 vr;
    vr.x = __float2bfloat16(qa - __bfloat162float(v.x));
    vr.y = __float2bfloat16(qb - __bfloat162float(v.y));
    *(__nv_bfloat162*)&ql[base] = vr;
    v.x = __float2bfloat16(k0); v.y = __float2bfloat16(k1);
    *(__nv_bfloat162*)&kh[base] = v;
    vr.x = __float2bfloat16(k0 - __bfloat162float(v.x));
    vr.y = __float2bfloat16(k1 - __bfloat162float(v.y));
    *(__nv_bfloat162*)&kl[base] = vr;
}

// ---------------- lambda scalar ----------------
__global__ void lambda_kernel(const float* __restrict__ lq1, const float* __restrict__ lk1,
                              const float* __restrict__ lq2, const float* __restrict__ lk2) {
    __shared__ float s1[64], s2[64];
    int t = threadIdx.x;
    s1[t] = lq1[t] * lk1[t];
    s2[t] = lq2[t] * lk2[t];
    __syncthreads();
    if (t == 0) {
        float a = 0.f, b = 0.f;
        for (int j = 0; j < 64; j++) { a += s1[j]; b += s2[j]; }
        g_lambda = expf(a) - expf(b) + LAMBDA_INIT;
    }
}

// ---------------- HMMA differential flash attention (unchanged from R11) ----------------
#define OQH 0
#define OQL 18432
#define OKH 36864
#define OKL 55296
#define OVH 73728
#define OVL 91136
#define ATT_SMEM 108544

__global__ __launch_bounds__(256) void diff_attn_mma(
    const __nv_bfloat16* __restrict__ qh, const __nv_bfloat16* __restrict__ ql,
    const __nv_bfloat16* __restrict__ kh, const __nv_bfloat16* __restrict__ kl,
    const __nv_bfloat16* __restrict__ vh, const __nv_bfloat16* __restrict__ vl,
    __nv_bfloat16* __restrict__ oh, __nv_bfloat16* __restrict__ ol) {
    extern __shared__ char sm[];
    const uint32_t sb = smem_u32(sm);
    const int tid = threadIdx.x;
    const int lane = tid & 31, wid = tid >> 5;
    const int wm = wid & 3, st = wid >> 2;
    const int h = blockIdx.y;
    const int q0 = blockIdx.x * 64;

#pragma unroll
    for (int j = 0; j < 8; j++) {
        int u = tid + j * 256;
        int arr = u >> 10, rem = u & 1023;
        int qst = rem >> 9, r2 = (rem >> 3) & 63, qq = rem & 7;
        const __nv_bfloat16* src = arr ? ql : qh;
        uint32_t off = (arr ? OQL : OQH) + (uint32_t)(qst * 64 + r2) * 144 + qq * 16;
        *(uint4*)(sm + off) =
            *(const uint4*)&src[(size_t)(q0 + r2) * E_DIM + (2 * h + qst) * 64 + qq * 8];
    }

    float O[16][4];
#pragma unroll
    for (int ct = 0; ct < 16; ct++)
#pragma unroll
        for (int i = 0; i < 4; i++) O[ct][i] = 0.f;
    float m0 = -INFINITY, m1 = -INFINITY, l0 = 0.f, l1 = 0.f;

    const int quarter = lane >> 3, wi = lane & 7;
    const uint32_t aoff_base = (uint32_t)(st * 64 + wm * 16 + (lane & 15)) * 144 + ((lane >> 4) * 16);
    const uint32_t voff_base = (uint32_t)((lane & 7) + ((lane & 8) ? 8 : 0)) * 272 + ((lane & 16) ? 16 : 0);

    for (int sbk = 0; sbk < 32; sbk++) {
        const int s0 = sbk * 64;
        __syncthreads();
#pragma unroll
        for (int j = 0; j < 8; j++) {
            int u = tid + j * 256;
            int arr = u >> 10, rem = u & 1023;
            int kst = rem >> 9, r2 = (rem >> 3) & 63, qq = rem & 7;
            const __nv_bfloat16* src = arr ? kl : kh;
            uint32_t off = (arr ? OKL : OKH) + (uint32_t)(kst * 64 + r2) * 144 + qq * 16;
            *(uint4*)(sm + off) =
                *(const uint4*)&src[(size_t)(s0 + r2) * E_DIM + (2 * h + kst) * 64 + qq * 8];
        }
#pragma unroll
        for (int j = 0; j < 8; j++) {
            int u = tid + j * 256;
            int arr = u >> 10, rem = u & 1023;
            int r2 = rem >> 4, qq = rem & 15;
            const __nv_bfloat16* src = arr ? vl : vh;
            uint32_t off = (arr ? OVL : OVH) + (uint32_t)r2 * 272 + qq * 16;
            *(uint4*)(sm + off) =
                *(const uint4*)&src[(size_t)(s0 + r2) * E_DIM + h * 128 + qq * 8];
        }
        __syncthreads();

        float sacc[8][4];
#pragma unroll
        for (int t = 0; t < 8; t++)
#pragma unroll
            for (int i = 0; i < 4; i++) sacc[t][i] = 0.f;

#pragma unroll
        for (int ks = 0; ks < 4; ks++) {
            uint32_t aQh[4], aQl[4];
            uint32_t ao = aoff_base + ks * 32;
            ldsm4(aQh, sb + OQH + ao);
            ldsm4(aQl, sb + OQL + ao);
#pragma unroll
            for (int p = 0; p < 4; p++) {
                uint32_t bo = (uint32_t)(st * 64 + p * 16 + (quarter >> 1) * 8 + wi) * 144
                              + ks * 32 + ((quarter & 1) * 16);
                uint32_t bh[4], bl[4];
                ldsm4(bh, sb + OKH + bo);
                ldsm4(bl, sb + OKL + bo);
                mma16816(sacc[2 * p], aQh, &bh[0]);
                mma16816(sacc[2 * p + 1], aQh, &bh[2]);
                mma16816(sacc[2 * p], aQh, &bl[0]);
                mma16816(sacc[2 * p + 1], aQh, &bl[2]);
                mma16816(sacc[2 * p], aQl, &bh[0]);
                mma16816(sacc[2 * p + 1], aQl, &bh[2]);
            }
        }

        float mx0 = -INFINITY, mx1 = -INFINITY;
#pragma unroll
        for (int t = 0; t < 8; t++) {
            mx0 = fmaxf(mx0, fmaxf(sacc[t][0], sacc[t][1]));
            mx1 = fmaxf(mx1, fmaxf(sacc[t][2], sacc[t][3]));
        }
        mx0 = fmaxf(mx0, __shfl_xor_sync(0xffffffffu, mx0, 1));
        mx0 = fmaxf(mx0, __shfl_xor_sync(0xffffffffu, mx0, 2));
        mx1 = fmaxf(mx1, __shfl_xor_sync(0xffffffffu, mx1, 1));
        mx1 = fmaxf(mx1, __shfl_xor_sync(0xffffffffu, mx1, 2));
        float mn0 = fmaxf(m0, mx0), mn1 = fmaxf(m1, mx1);
        float al0 = __expf(m0 - mn0), al1 = __expf(m1 - mn1);
        m0 = mn0; m1 = mn1;

        uint32_t aPh[4][4], aPl[4][4];
        float rs0 = 0.f, rs1 = 0.f;
#pragma unroll
        for (int t = 0; t < 8; t++) {
            float p0 = __expf(sacc[t][0] - mn0);
            float p1 = __expf(sacc[t][1] - mn0);
            float p2 = __expf(sacc[t][2] - mn1);
            float p3 = __expf(sacc[t][3] - mn1);
            rs0 += p0 + p1; rs1 += p2 + p3;
            int j = t >> 1, hf = t & 1;
            __nv_bfloat162 hv, lv;
            hv.x = __float2bfloat16(p0); hv.y = __float2bfloat16(p1);
            lv.x = __float2bfloat16(p0 - __bfloat162float(hv.x));
            lv.y = __float2bfloat16(p1 - __bfloat162float(hv.y));
            aPh[j][hf * 2] = *(uint32_t*)&hv;
            aPl[j][hf * 2] = *(uint32_t*)&lv;
            hv.x = __float2bfloat16(p2); hv.y = __float2bfloat16(p3);
            lv.x = __float2bfloat16(p2 - __bfloat162float(hv.x));
            lv.y = __float2bfloat16(p3 - __bfloat162float(hv.y));
            aPh[j][hf * 2 + 1] = *(uint32_t*)&hv;
            aPl[j][hf * 2 + 1] = *(uint32_t*)&lv;
        }
        rs0 += __shfl_xor_sync(0xffffffffu, rs0, 1);
        rs0 += __shfl_xor_sync(0xffffffffu, rs0, 2);
        rs1 += __shfl_xor_sync(0xffffffffu, rs1, 1);
        rs1 += __shfl_xor_sync(0xffffffffu, rs1, 2);
        l0 = l0 * al0 + rs0;
        l1 = l1 * al1 + rs1;
#pragma unroll
        for (int ct = 0; ct < 16; ct++) {
            O[ct][0] *= al0; O[ct][1] *= al0;
            O[ct][2] *= al1; O[ct][3] *= al1;
        }

#pragma unroll
        for (int p8 = 0; p8 < 8; p8++) {
#pragma unroll
            for (int j = 0; j < 4; j++) {
                uint32_t vo = voff_base + (uint32_t)(j * 16) * 272 + p8 * 32;
                uint32_t bh[4], bl[4];
                ldsm4t(bh, sb + OVH + vo);
                ldsm4t(bl, sb + OVL + vo);
                mma16816(O[2 * p8], aPh[j], &bh[0]);
                mma16816(O[2 * p8 + 1], aPh[j], &bh[2]);
                mma16816(O[2 * p8], aPh[j], &bl[0]);
                mma16816(O[2 * p8 + 1], aPh[j], &bl[2]);
                mma16816(O[2 * p8], aPl[j], &bh[0]);
                mma16816(O[2 * p8 + 1], aPl[j], &bh[2]);
            }
        }
    }

    __syncthreads();
    {
        float* buf = (float*)(sm + (st ? 36864 : 0));
        float inv0 = 1.0f / l0, inv1 = 1.0f / l1;
        int r = wm * 16 + (lane >> 2);
#pragma unroll
        for (int ct = 0; ct < 16; ct++) {
            int c = ct * 8 + 2 * (lane & 3);
            *(float2*)&buf[r * 128 + c] = make_float2(O[ct][0] * inv0, O[ct][1] * inv0);
            *(float2*)&buf[(r + 8) * 128 + c] = make_float2(O[ct][2] * inv1, O[ct][3] * inv1);
        }
    }
    __syncthreads();
    {
        const float lam = g_lambda;
        const float* b0 = (const float*)sm;
        const float* b1 = (const float*)(sm + 36864);
        int r = tid >> 2, qt = tid & 3;
        float vals[32];
        float ss = 0.f;
#pragma unroll
        for (int i = 0; i < 32; i++) {
            int c = qt * 32 + i;
            float d = b0[r * 128 + c] - lam * b1[r * 128 + c];
            vals[i] = d;
            ss += d * d;
        }
        ss += __shfl_xor_sync(0xffffffffu, ss, 1);
        ss += __shfl_xor_sync(0xffffffffu, ss, 2);
        float g = rsqrtf(ss * (1.0f / 128.0f) + 1e-5f) * (1.0f - LAMBDA_INIT);
        size_t base = (size_t)(q0 + r) * E_DIM + h * 128 + qt * 32;
#pragma unroll
        for (int i = 0; i < 32; i += 2) {
            float o0 = vals[i] * g, o1 = vals[i + 1] * g;
            __nv_bfloat162 hv, lv;
            hv.x = __float2bfloat16(o0); hv.y = __float2bfloat16(o1);
            lv.x = __float2bfloat16(o0 - __bfloat162float(hv.x));
            lv.y = __float2bfloat16(o1 - __bfloat162float(hv.y));
            *(__nv_bfloat162*)&oh[base + i] = hv;
            *(__nv_bfloat162*)&ol[base + i] = lv;
        }
    }
}

// ---------------- launch ----------------
extern "C" void kernel_launch(void* const* d_in, const int* in_sizes, int n_in,
                              void* d_out, int out_size) {
    const float* x   = (const float*)d_in[0];
    const float* Wq  = (const float*)d_in[1];
    const float* Wk  = (const float*)d_in[2];
    const float* Wv  = (const float*)d_in[3];
    const float* Wo  = (const float*)d_in[4];
    const float* lq1 = (const float*)d_in[5];
    const float* lk1 = (const float*)d_in[6];
    const float* lq2 = (const float*)d_in[7];
    const float* lk2 = (const float*)d_in[8];
    float* out = (float*)d_out;

    float *pq, *pk, *pv, *ptab;
    cudaGetSymbolAddress((void**)&pq, g_q);
    cudaGetSymbolAddress((void**)&pk, g_k);
    cudaGetSymbolAddress((void**)&pv, g_v);
    cudaGetSymbolAddress((void**)&ptab, g_rope);

    __nv_bfloat16 *xh, *xl, *ah, *al, *qbh, *qbl, *kbh, *kbl, *vbh, *vbl;
    __nv_bfloat16 *wqh, *wql, *wkh, *wkl, *wvh, *wvl, *woh, *wol;
    cudaGetSymbolAddress((void**)&xh, g_xh);   cudaGetSymbolAddress((void**)&xl, g_xl);
    cudaGetSymbolAddress((void**)&ah, g_ah);   cudaGetSymbolAddress((void**)&al, g_al);
    cudaGetSymbolAddress((void**)&qbh, g_qbh); cudaGetSymbolAddress((void**)&qbl, g_qbl);
    cudaGetSymbolAddress((void**)&kbh, g_kbh); cudaGetSymbolAddress((void**)&kbl, g_kbl);
    cudaGetSymbolAddress((void**)&vbh, g_vbh); cudaGetSymbolAddress((void**)&vbl, g_vbl);
    cudaGetSymbolAddress((void**)&wqh, g_wqh); cudaGetSymbolAddress((void**)&wql, g_wql);
    cudaGetSymbolAddress((void**)&wkh, g_wkh); cudaGetSymbolAddress((void**)&wkl, g_wkl);
    cudaGetSymbolAddress((void**)&wvh, g_wvh); cudaGetSymbolAddress((void**)&wvl, g_wvl);
    cudaGetSymbolAddress((void**)&woh, g_woh); cudaGetSymbolAddress((void**)&wol, g_wol);

    cudaFuncSetAttribute(gemm_hmma, cudaFuncAttributeMaxDynamicSharedMemorySize, GEMM_SMEM);
    cudaFuncSetAttribute(diff_attn_mma, cudaFuncAttributeMaxDynamicSharedMemorySize, ATT_SMEM);

    const int nX = T_SEQ * E_DIM;
    const int nW = E_DIM * E_DIM;
    cvt_split<<<(nX + 255) / 256, 256>>>(x, xh, xl, nX);
    cvt_weights<<<dim3(nW / 256, 4), 256>>>(Wq, Wk, Wv, Wo, wqh, wql, wkh, wkl,
                                            wvh, wvl, woh, wol);

    rope_tables<<<T_SEQ, 32>>>(ptab);
    lambda_kernel<<<1, 64>>>(lq1, lk1, lq2, lk2);

    // fused Q/K/V projections (z selects weight/output)
    gemm_hmma<<<dim3(E_DIM / 128, T_SEQ / 128, 3), 512, GEMM_SMEM>>>(
        xh, xl, wqh, wql, wkh, wkl, wvh, wvl, pq, pk, pv, T_SEQ, E_DIM, E_DIM);

    rope_apply<<<T_SEQ, 512>>>(pq, pk, ptab, qbh, qbl, kbh, kbl);
    cvt_split<<<(nX + 255) / 256, 256>>>(pv, vbh, vbl, nX);

    diff_attn_mma<<<dim3(T_SEQ / 64, NH), 256, ATT_SMEM>>>(qbh, qbl, kbh, kbl, vbh, vbl, ah, al);

    // output projection
    gemm_hmma<<<dim3(E_DIM / 128, T_SEQ / 128, 1), 512, GEMM_SMEM>>>(
        ah, al, woh, wol, woh, wol, woh, wol, out, out, out, T_SEQ, E_DIM, E_DIM);
}

// round 16
// speedup vs baseline: 1.1371x; 1.1371x over previous
#include <cuda_runtime.h>
#include <cuda_fp16.h>
#include <cstdint>
#include <math.h>

#define T_SEQ 2048
#define E_DIM 1024
#define NH 8
#define LAMBDA_INIT 0.35550906759096927f

// ---------------- scratch (device globals; no runtime allocation) ----------------
__device__ float g_q[T_SEQ * E_DIM];
__device__ float g_k[T_SEQ * E_DIM];
__device__ float g_v[T_SEQ * E_DIM];
__device__ float g_lambda;
__device__ float g_rope[T_SEQ * 32 * 4];

__device__ __half g_xh[T_SEQ * E_DIM], g_xl[T_SEQ * E_DIM];
__device__ __half g_ah[T_SEQ * E_DIM], g_al[T_SEQ * E_DIM];
__device__ __half g_qbh[T_SEQ * E_DIM], g_qbl[T_SEQ * E_DIM];
__device__ __half g_kbh[T_SEQ * E_DIM], g_kbl[T_SEQ * E_DIM];
__device__ __half g_vbh[T_SEQ * E_DIM];
__device__ __half g_wqh[E_DIM * E_DIM], g_wql[E_DIM * E_DIM];
__device__ __half g_wkh[E_DIM * E_DIM], g_wkl[E_DIM * E_DIM];
__device__ __half g_wvh[E_DIM * E_DIM], g_wvl[E_DIM * E_DIM];
__device__ __half g_woh[E_DIM * E_DIM], g_wol[E_DIM * E_DIM];

// ---------------- warp-MMA helpers (baseline PTX, works at sm_103 non-a) ----------------
__device__ __forceinline__ uint32_t smem_u32(const void* p) {
    uint32_t a;
    asm("{ .reg .u64 t; cvta.to.shared.u64 t, %1; cvt.u32.u64 %0, t; }" : "=r"(a) : "l"(p));
    return a;
}
__device__ __forceinline__ void ldsm4(uint32_t* r, uint32_t addr) {
    asm volatile("ldmatrix.sync.aligned.m8n8.x4.shared.b16 {%0,%1,%2,%3}, [%4];"
                 : "=r"(r[0]), "=r"(r[1]), "=r"(r[2]), "=r"(r[3]) : "r"(addr));
}
__device__ __forceinline__ void ldsm4t(uint32_t* r, uint32_t addr) {
    asm volatile("ldmatrix.sync.aligned.m8n8.x4.trans.shared.b16 {%0,%1,%2,%3}, [%4];"
                 : "=r"(r[0]), "=r"(r[1]), "=r"(r[2]), "=r"(r[3]) : "r"(addr));
}
// f16 inputs, f32 accumulate
__device__ __forceinline__ void mma16816(float* d, const uint32_t* a, const uint32_t* b) {
    asm volatile("mma.sync.aligned.m16n8k16.row.col.f32.f16.f16.f32 "
                 "{%0,%1,%2,%3}, {%4,%5,%6,%7}, {%8,%9}, {%0,%1,%2,%3};"
                 : "+f"(d[0]), "+f"(d[1]), "+f"(d[2]), "+f"(d[3])
                 : "r"(a[0]), "r"(a[1]), "r"(a[2]), "r"(a[3]), "r"(b[0]), "r"(b[1]));
}
__device__ __forceinline__ void cpa16(uint32_t s, const void* g) {
    asm volatile("cp.async.ca.shared.global [%0], [%1], 16;" :: "r"(s), "l"(g));
}
#define CPA_COMMIT() asm volatile("cp.async.commit_group;" ::: "memory")
#define CPA_WAIT(n)  asm volatile("cp.async.wait_group %0;" :: "n"(n) : "memory")

// ---------------- split-fp16 conversion ----------------
__global__ void cvt_split(const float* __restrict__ in, __half* __restrict__ hi,
                          __half* __restrict__ lo, int n) {
    int i = blockIdx.x * 256 + threadIdx.x;
    if (i < n) {
        float v = in[i];
        __half h = __float2half(v);
        hi[i] = h;
        lo[i] = __float2half(v - __half2float(h));
    }
}
__global__ void cvt_single(const float* __restrict__ in, __half* __restrict__ hi, int n) {
    int i = blockIdx.x * 256 + threadIdx.x;
    if (i < n) hi[i] = __float2half(in[i]);
}

// fused cvt for 4 weight matrices (blockIdx.y selects)
__global__ void cvt_weights(const float* __restrict__ Wq, const float* __restrict__ Wk,
                            const float* __restrict__ Wv, const float* __restrict__ Wo,
                            __half* __restrict__ qh, __half* __restrict__ ql,
                            __half* __restrict__ kh, __half* __restrict__ kl,
                            __half* __restrict__ vh, __half* __restrict__ vl,
                            __half* __restrict__ oh, __half* __restrict__ ol) {
    int i = blockIdx.x * 256 + threadIdx.x;
    int w = blockIdx.y;
    const float* src = (w == 0) ? Wq : (w == 1) ? Wk : (w == 2) ? Wv : Wo;
    __half* hi = (w == 0) ? qh : (w == 1) ? kh : (w == 2) ? vh : oh;
    __half* lo = (w == 0) ? ql : (w == 1) ? kl : (w == 2) ? vl : ol;
    float v = src[i];
    __half h = __float2half(v);
    hi[i] = h;
    lo[i] = __float2half(v - __half2float(h));
}

// ---------------- HMMA GEMM (cp.async double-buffered, 256 thr): C = A * B^T ----------------
// CTA 128x128, 8 warps (4M x 2N), warp tile 32x64, K-chunk 32. blockIdx.z selects (B, C).
// t3mask bit z: 1 = three-term (Ah*Bh + Ah*Bl + Al*Bh), 0 = two-term (Ah*Bh + Al*Bh).
#define GSROW 40
#define GARR 10240
#define GBUFB 40960
#define GEMM_SMEM 81920

__global__ __launch_bounds__(256) void gemm_hmma(
    const __half* __restrict__ Ah, const __half* __restrict__ Al,
    const __half* __restrict__ B0h, const __half* __restrict__ B0l,
    const __half* __restrict__ B1h, const __half* __restrict__ B1l,
    const __half* __restrict__ B2h, const __half* __restrict__ B2l,
    float* __restrict__ C0, float* __restrict__ C1, float* __restrict__ C2,
    unsigned t3mask, int M, int N, int K) {
    extern __shared__ char dsm[];
    const uint32_t sb = smem_u32(dsm);

    const int tid = threadIdx.x;
    const int lane = tid & 31, wid = tid >> 5;
    const int wm = wid & 3, wn = wid >> 2;
    const int m0 = blockIdx.y * 128, n0 = blockIdx.x * 128;
    const int z = blockIdx.z;
    const bool t3 = (t3mask >> z) & 1u;
    const __half* Bh = (z == 0) ? B0h : (z == 1) ? B1h : B2h;
    const __half* Bl = (z == 0) ? B0l : (z == 1) ? B1l : B2l;
    float* C = (z == 0) ? C0 : (z == 1) ? C1 : C2;

    float acc[2][8][4];
#pragma unroll
    for (int mt = 0; mt < 2; mt++)
#pragma unroll
        for (int nt = 0; nt < 8; nt++)
#pragma unroll
            for (int i = 0; i < 4; i++) acc[mt][nt][i] = 0.f;

    int rowA[2], qA[2];
#pragma unroll
    for (int j = 0; j < 2; j++) {
        int u = tid + j * 256;
        rowA[j] = u >> 2;
        qA[j] = u & 3;
    }

    const int nchunk = K >> 5;

    auto load_chunk = [&](int c, int b) {
        int k0 = c << 5;
        uint32_t bs = sb + b * GBUFB;
#pragma unroll
        for (int j = 0; j < 2; j++) {
            uint32_t so = (uint32_t)(rowA[j] * GSROW + qA[j] * 8) * 2;
            size_t ga = (size_t)(m0 + rowA[j]) * K + k0 + qA[j] * 8;
            size_t gb = (size_t)(n0 + rowA[j]) * K + k0 + qA[j] * 8;
            cpa16(bs + so, &Ah[ga]);
            cpa16(bs + GARR + so, &Al[ga]);
            cpa16(bs + 2 * GARR + so, &Bh[gb]);
            if (t3) cpa16(bs + 3 * GARR + so, &Bl[gb]);
        }
        CPA_COMMIT();
    };

    load_chunk(0, 0);
    load_chunk(1, 1);

    const int quarter = lane >> 3, wi = lane & 7;

    for (int c = 0; c < nchunk; c++) {
        const int buf = c & 1;
        if (c + 1 < nchunk) CPA_WAIT(1); else CPA_WAIT(0);
        __syncthreads();

        const uint32_t uAh = sb + buf * GBUFB;
        const uint32_t uAl = uAh + GARR;
        const uint32_t uBh = uAh + 2 * GARR;
        const uint32_t uBl = uAh + 3 * GARR;

#pragma unroll
        for (int ks = 0; ks < 2; ks++) {
            uint32_t aH[2][4], aL[2][4], bH[16], bL[16];
#pragma unroll
            for (int mt = 0; mt < 2; mt++) {
                uint32_t off = (uint32_t)(wm * 32 + mt * 16 + (lane & 15)) * (GSROW * 2)
                               + ks * 32 + ((lane >> 4) * 16);
                ldsm4(aH[mt], uAh + off);
                ldsm4(aL[mt], uAl + off);
            }
#pragma unroll
            for (int p = 0; p < 4; p++) {
                uint32_t off = (uint32_t)(wn * 64 + p * 16 + (quarter >> 1) * 8 + wi) * (GSROW * 2)
                               + ks * 32 + ((quarter & 1) * 16);
                ldsm4(&bH[p * 4], uBh + off);
                if (t3) ldsm4(&bL[p * 4], uBl + off);
            }
#pragma unroll
            for (int mt = 0; mt < 2; mt++)
#pragma unroll
                for (int nt = 0; nt < 8; nt++) {
                    mma16816(acc[mt][nt], aH[mt], &bH[nt * 2]);
                    mma16816(acc[mt][nt], aL[mt], &bH[nt * 2]);
                    if (t3) mma16816(acc[mt][nt], aH[mt], &bL[nt * 2]);
                }
        }
        __syncthreads();
        if (c + 2 < nchunk) load_chunk(c + 2, buf);
    }

#pragma unroll
    for (int mt = 0; mt < 2; mt++) {
        int row = m0 + wm * 32 + mt * 16 + (lane >> 2);
#pragma unroll
        for (int nt = 0; nt < 8; nt++) {
            int col = n0 + wn * 64 + nt * 8 + (lane & 3) * 2;
            float2 v0 = make_float2(acc[mt][nt][0], acc[mt][nt][1]);
            float2 v1 = make_float2(acc[mt][nt][2], acc[mt][nt][3]);
            *(float2*)&C[(size_t)row * N + col] = v0;
            *(float2*)&C[(size_t)(row + 8) * N + col] = v1;
        }
    }
}

// ---------------- RoPE tables (tiny fp64 kernel) ----------------
__global__ void rope_tables(float* __restrict__ tab) {
    int t = blockIdx.x;
    int i = threadIdx.x;
    double inv = pow(10000.0, -(double)i / 32.0);
    double f = fmod((double)t * inv, 6.283185307179586);
    float cf = (float)cos(f), sf = (float)sin(f);
    float power = ((float)t - 1024.0f) / 512.0f;
    int je = (2 * i) & 31, jo = (2 * i + 1) & 31;
    float sv_e = (2.0f * je + 25.6f) / 89.6f;
    float sv_o = (2.0f * jo + 25.6f) / 89.6f;
    float se = powf(sv_e, power), so = powf(sv_o, power);
    int idx = (t * 32 + i) * 4;
    tab[idx] = cf; tab[idx + 1] = sf; tab[idx + 2] = se; tab[idx + 3] = so;
}

// ---------------- RoPE apply: fp32 in -> split fp16 out ----------------
__global__ void rope_apply(const float* __restrict__ q, const float* __restrict__ k,
                           const float* __restrict__ tab,
                           __half* __restrict__ qh, __half* __restrict__ ql,
                           __half* __restrict__ kh, __half* __restrict__ kl) {
    int t = blockIdx.x;
    int p = threadIdx.x;
    int head = p >> 5;
    int i = p & 31;
    float4 tv = *(const float4*)&tab[(t * 32 + i) * 4];
    float cf = tv.x, sf = tv.y, se = tv.z, so = tv.w;

    size_t base = (size_t)t * E_DIM + head * 64 + 2 * i;
    float a = q[base], b = q[base + 1];
    float qa = (a * cf - b * sf) * se * 0.125f;
    float qb = (b * cf + a * sf) * so * 0.125f;
    float ka = k[base], kb = k[base + 1];
    float k0 = (ka * cf - kb * sf) / se;
    float k1 = (kb * cf + ka * sf) / so;

    __half2 v, vr;
    v.x = __float2half(qa); v.y = __float2half(qb);
    *(__half2*)&qh[base] = v;
    vr.x = __float2half(qa - __half2float(v.x));
    vr.y = __float2half(qb - __half2float(v.y));
    *(__half2*)&ql[base] = vr;
    v.x = __float2half(k0); v.y = __float2half(k1);
    *(__half2*)&kh[base] = v;
    vr.x = __float2half(k0 - __half2float(v.x));
    vr.y = __float2half(k1 - __half2float(v.y));
    *(__half2*)&kl[base] = vr;
}

// ---------------- lambda scalar ----------------
__global__ void lambda_kernel(const float* __restrict__ lq1, const float* __restrict__ lk1,
                              const float* __restrict__ lq2, const float* __restrict__ lk2) {
    __shared__ float s1[64], s2[64];
    int t = threadIdx.x;
    s1[t] = lq1[t] * lk1[t];
    s2[t] = lq2[t] * lk2[t];
    __syncthreads();
    if (t == 0) {
        float a = 0.f, b = 0.f;
        for (int j = 0; j < 64; j++) { a += s1[j]; b += s2[j]; }
        g_lambda = expf(a) - expf(b) + LAMBDA_INIT;
    }
}

// ---------------- HMMA differential flash attention (fp16; V single-term) ----------------
// Smem: Qh [2st][64][144B] @0, Ql @18432, Kh @36864, Kl @55296, Vh [64][272B] @73728
#define OQH 0
#define OQL 18432
#define OKH 36864
#define OKL 55296
#define OVH 73728
#define ATT_SMEM 91136

__global__ __launch_bounds__(256) void diff_attn_mma(
    const __half* __restrict__ qh, const __half* __restrict__ ql,
    const __half* __restrict__ kh, const __half* __restrict__ kl,
    const __half* __restrict__ vh,
    __half* __restrict__ oh, __half* __restrict__ ol) {
    extern __shared__ char sm[];
    const uint32_t sb = smem_u32(sm);
    const int tid = threadIdx.x;
    const int lane = tid & 31, wid = tid >> 5;
    const int wm = wid & 3, st = wid >> 2;
    const int h = blockIdx.y;
    const int q0 = blockIdx.x * 64;

    // ---- load Q (both streams, hi/lo): 2048 uint4 ----
#pragma unroll
    for (int j = 0; j < 8; j++) {
        int u = tid + j * 256;
        int arr = u >> 10, rem = u & 1023;
        int qst = rem >> 9, r2 = (rem >> 3) & 63, qq = rem & 7;
        const __half* src = arr ? ql : qh;
        uint32_t off = (arr ? OQL : OQH) + (uint32_t)(qst * 64 + r2) * 144 + qq * 16;
        *(uint4*)(sm + off) =
            *(const uint4*)&src[(size_t)(q0 + r2) * E_DIM + (2 * h + qst) * 64 + qq * 8];
    }

    float O[16][4];
#pragma unroll
    for (int ct = 0; ct < 16; ct++)
#pragma unroll
        for (int i = 0; i < 4; i++) O[ct][i] = 0.f;
    float m0 = -INFINITY, m1 = -INFINITY, l0 = 0.f, l1 = 0.f;

    const int quarter = lane >> 3, wi = lane & 7;
    const uint32_t aoff_base = (uint32_t)(st * 64 + wm * 16 + (lane & 15)) * 144 + ((lane >> 4) * 16);
    const uint32_t voff_base = (uint32_t)((lane & 7) + ((lane & 8) ? 8 : 0)) * 272 + ((lane & 16) ? 16 : 0);

    for (int sbk = 0; sbk < 32; sbk++) {
        const int s0 = sbk * 64;
        __syncthreads();
        // ---- K hi/lo: 2048 uint4 ----
#pragma unroll
        for (int j = 0; j < 8; j++) {
            int u = tid + j * 256;
            int arr = u >> 10, rem = u & 1023;
            int kst = rem >> 9, r2 = (rem >> 3) & 63, qq = rem & 7;
            const __half* src = arr ? kl : kh;
            uint32_t off = (arr ? OKL : OKH) + (uint32_t)(kst * 64 + r2) * 144 + qq * 16;
            *(uint4*)(sm + off) =
                *(const uint4*)&src[(size_t)(s0 + r2) * E_DIM + (2 * h + kst) * 64 + qq * 8];
        }
        // ---- V single: 1024 uint4 ----
#pragma unroll
        for (int j = 0; j < 4; j++) {
            int u = tid + j * 256;
            int r2 = u >> 4, qq = u & 15;
            uint32_t off = OVH + (uint32_t)r2 * 272 + qq * 16;
            *(uint4*)(sm + off) =
                *(const uint4*)&vh[(size_t)(s0 + r2) * E_DIM + h * 128 + qq * 8];
        }
        __syncthreads();

        // ---- S = Q_st * K_st^T (3-term fp16 split) ----
        float sacc[8][4];
#pragma unroll
        for (int t = 0; t < 8; t++)
#pragma unroll
            for (int i = 0; i < 4; i++) sacc[t][i] = 0.f;

#pragma unroll
        for (int ks = 0; ks < 4; ks++) {
            uint32_t aQh[4], aQl[4];
            uint32_t ao = aoff_base + ks * 32;
            ldsm4(aQh, sb + OQH + ao);
            ldsm4(aQl, sb + OQL + ao);
#pragma unroll
            for (int p = 0; p < 4; p++) {
                uint32_t bo = (uint32_t)(st * 64 + p * 16 + (quarter >> 1) * 8 + wi) * 144
                              + ks * 32 + ((quarter & 1) * 16);
                uint32_t bh[4], bl[4];
                ldsm4(bh, sb + OKH + bo);
                ldsm4(bl, sb + OKL + bo);
                mma16816(sacc[2 * p], aQh, &bh[0]);
                mma16816(sacc[2 * p + 1], aQh, &bh[2]);
                mma16816(sacc[2 * p], aQh, &bl[0]);
                mma16816(sacc[2 * p + 1], aQh, &bl[2]);
                mma16816(sacc[2 * p], aQl, &bh[0]);
                mma16816(sacc[2 * p + 1], aQl, &bh[2]);
            }
        }

        // ---- online softmax ----
        float mx0 = -INFINITY, mx1 = -INFINITY;
#pragma unroll
        for (int t = 0; t < 8; t++) {
            mx0 = fmaxf(mx0, fmaxf(sacc[t][0], sacc[t][1]));
            mx1 = fmaxf(mx1, fmaxf(sacc[t][2], sacc[t][3]));
        }
        mx0 = fmaxf(mx0, __shfl_xor_sync(0xffffffffu, mx0, 1));
        mx0 = fmaxf(mx0, __shfl_xor_sync(0xffffffffu, mx0, 2));
        mx1 = fmaxf(mx1, __shfl_xor_sync(0xffffffffu, mx1, 1));
        mx1 = fmaxf(mx1, __shfl_xor_sync(0xffffffffu, mx1, 2));
        float mn0 = fmaxf(m0, mx0), mn1 = fmaxf(m1, mx1);
        float al0 = __expf(m0 - mn0), al1 = __expf(m1 - mn1);
        m0 = mn0; m1 = mn1;

        uint32_t aPh[4][4], aPl[4][4];
        float rs0 = 0.f, rs1 = 0.f;
#pragma unroll
        for (int t = 0; t < 8; t++) {
            float p0 = __expf(sacc[t][0] - mn0);
            float p1 = __expf(sacc[t][1] - mn0);
            float p2 = __expf(sacc[t][2] - mn1);
            float p3 = __expf(sacc[t][3] - mn1);
            rs0 += p0 + p1; rs1 += p2 + p3;
            int j = t >> 1, hf = t & 1;
            __half2 hv, lv;
            hv.x = __float2half(p0); hv.y = __float2half(p1);
            lv.x = __float2half(p0 - __half2float(hv.x));
            lv.y = __float2half(p1 - __half2float(hv.y));
            aPh[j][hf * 2] = *(uint32_t*)&hv;
            aPl[j][hf * 2] = *(uint32_t*)&lv;
            hv.x = __float2half(p2); hv.y = __float2half(p3);
            lv.x = __float2half(p2 - __half2float(hv.x));
            lv.y = __float2half(p3 - __half2float(hv.y));
            aPh[j][hf * 2 + 1] = *(uint32_t*)&hv;
            aPl[j][hf * 2 + 1] = *(uint32_t*)&lv;
        }
        rs0 += __shfl_xor_sync(0xffffffffu, rs0, 1);
        rs0 += __shfl_xor_sync(0xffffffffu, rs0, 2);
        rs1 += __shfl_xor_sync(0xffffffffu, rs1, 1);
        rs1 += __shfl_xor_sync(0xffffffffu, rs1, 2);
        l0 = l0 * al0 + rs0;
        l1 = l1 * al1 + rs1;
#pragma unroll
        for (int ct = 0; ct < 16; ct++) {
            O[ct][0] *= al0; O[ct][1] *= al0;
            O[ct][2] *= al1; O[ct][3] *= al1;
        }

        // ---- O += P * V (P 2-term split, V single) ----
#pragma unroll
        for (int p8 = 0; p8 < 8; p8++) {
#pragma unroll
            for (int j = 0; j < 4; j++) {
                uint32_t vo = voff_base + (uint32_t)(j * 16) * 272 + p8 * 32;
                uint32_t bh[4];
                ldsm4t(bh, sb + OVH + vo);
                mma16816(O[2 * p8], aPh[j], &bh[0]);
                mma16816(O[2 * p8 + 1], aPh[j], &bh[2]);
                mma16816(O[2 * p8], aPl[j], &bh[0]);
                mma16816(O[2 * p8 + 1], aPl[j], &bh[2]);
            }
        }
    }

    // ---- epilogue: normalize, diff, RMS, split-fp16 out ----
    __syncthreads();
    {
        float* buf = (float*)(sm + (st ? 36864 : 0));
        float inv0 = 1.0f / l0, inv1 = 1.0f / l1;
        int r = wm * 16 + (lane >> 2);
#pragma unroll
        for (int ct = 0; ct < 16; ct++) {
            int c = ct * 8 + 2 * (lane & 3);
            *(float2*)&buf[r * 128 + c] = make_float2(O[ct][0] * inv0, O[ct][1] * inv0);
            *(float2*)&buf[(r + 8) * 128 + c] = make_float2(O[ct][2] * inv1, O[ct][3] * inv1);
        }
    }
    __syncthreads();
    {
        const float lam = g_lambda;
        const float* b0 = (const float*)sm;
        const float* b1 = (const float*)(sm + 36864);
        int r = tid >> 2, qt = tid & 3;
        float vals[32];
        float ss = 0.f;
#pragma unroll
        for (int i = 0; i < 32; i++) {
            int c = qt * 32 + i;
            float d = b0[r * 128 + c] - lam * b1[r * 128 + c];
            vals[i] = d;
            ss += d * d;
        }
        ss += __shfl_xor_sync(0xffffffffu, ss, 1);
        ss += __shfl_xor_sync(0xffffffffu, ss, 2);
        float g = rsqrtf(ss * (1.0f / 128.0f) + 1e-5f) * (1.0f - LAMBDA_INIT);
        size_t base = (size_t)(q0 + r) * E_DIM + h * 128 + qt * 32;
#pragma unroll
        for (int i = 0; i < 32; i += 2) {
            float o0 = vals[i] * g, o1 = vals[i + 1] * g;
            __half2 hv, lv;
            hv.x = __float2half(o0); hv.y = __float2half(o1);
            lv.x = __float2half(o0 - __half2float(hv.x));
            lv.y = __float2half(o1 - __half2float(hv.y));
            *(__half2*)&oh[base + i] = hv;
            *(__half2*)&ol[base + i] = lv;
        }
    }
}

// ---------------- launch ----------------
extern "C" void kernel_launch(void* const* d_in, const int* in_sizes, int n_in,
                              void* d_out, int out_size) {
    const float* x   = (const float*)d_in[0];
    const float* Wq  = (const float*)d_in[1];
    const float* Wk  = (const float*)d_in[2];
    const float* Wv  = (const float*)d_in[3];
    const float* Wo  = (const float*)d_in[4];
    const float* lq1 = (const float*)d_in[5];
    const float* lk1 = (const float*)d_in[6];
    const float* lq2 = (const float*)d_in[7];
    const float* lk2 = (const float*)d_in[8];
    float* out = (float*)d_out;

    float *pq, *pk, *pv, *ptab;
    cudaGetSymbolAddress((void**)&pq, g_q);
    cudaGetSymbolAddress((void**)&pk, g_k);
    cudaGetSymbolAddress((void**)&pv, g_v);
    cudaGetSymbolAddress((void**)&ptab, g_rope);

    __half *xh, *xl, *ah, *al, *qbh, *qbl, *kbh, *kbl, *vbh;
    __half *wqh, *wql, *wkh, *wkl, *wvh, *wvl, *woh, *wol;
    cudaGetSymbolAddress((void**)&xh, g_xh);   cudaGetSymbolAddress((void**)&xl, g_xl);
    cudaGetSymbolAddress((void**)&ah, g_ah);   cudaGetSymbolAddress((void**)&al, g_al);
    cudaGetSymbolAddress((void**)&qbh, g_qbh); cudaGetSymbolAddress((void**)&qbl, g_qbl);
    cudaGetSymbolAddress((void**)&kbh, g_kbh); cudaGetSymbolAddress((void**)&kbl, g_kbl);
    cudaGetSymbolAddress((void**)&vbh, g_vbh);
    cudaGetSymbolAddress((void**)&wqh, g_wqh); cudaGetSymbolAddress((void**)&wql, g_wql);
    cudaGetSymbolAddress((void**)&wkh, g_wkh); cudaGetSymbolAddress((void**)&wkl, g_wkl);
    cudaGetSymbolAddress((void**)&wvh, g_wvh); cudaGetSymbolAddress((void**)&wvl, g_wvl);
    cudaGetSymbolAddress((void**)&woh, g_woh); cudaGetSymbolAddress((void**)&wol, g_wol);

    cudaFuncSetAttribute(gemm_hmma, cudaFuncAttributeMaxDynamicSharedMemorySize, GEMM_SMEM);
    cudaFuncSetAttribute(diff_attn_mma, cudaFuncAttributeMaxDynamicSharedMemorySize, ATT_SMEM);

    const int nX = T_SEQ * E_DIM;
    const int nW = E_DIM * E_DIM;
    cvt_split<<<(nX + 255) / 256, 256>>>(x, xh, xl, nX);
    cvt_weights<<<dim3(nW / 256, 4), 256>>>(Wq, Wk, Wv, Wo, wqh, wql, wkh, wkl,
                                            wvh, wvl, woh, wol);

    rope_tables<<<T_SEQ, 32>>>(ptab);
    lambda_kernel<<<1, 64>>>(lq1, lk1, lq2, lk2);

    // fused Q/K/V projections: q,k 3-term (logit-sensitive), v 2-term
    gemm_hmma<<<dim3(E_DIM / 128, T_SEQ / 128, 3), 256, GEMM_SMEM>>>(
        xh, xl, wqh, wql, wkh, wkl, wvh, wvl, pq, pk, pv, 0b011u, T_SEQ, E_DIM, E_DIM);

    rope_apply<<<T_SEQ, 512>>>(pq, pk, ptab, qbh, qbl, kbh, kbl);
    cvt_single<<<(nX + 255) / 256, 256>>>(pv, vbh, nX);

    diff_attn_mma<<<dim3(T_SEQ / 64, NH), 256, ATT_SMEM>>>(qbh, qbl, kbh, kbl, vbh, ah, al);

    // output projection: 2-term
    gemm_hmma<<<dim3(E_DIM / 128, T_SEQ / 128, 1), 256, GEMM_SMEM>>>(
        ah, al, woh, wol, woh, wol, woh, wol, out, out, out, 0u, T_SEQ, E_DIM, E_DIM);
}

// round 17
// speedup vs baseline: 1.4279x; 1.2558x over previous
#include <cuda_runtime.h>
#include <cuda_fp16.h>
#include <cstdint>
#include <math.h>

#define T_SEQ 2048
#define E_DIM 1024
#define NH 8
#define LAMBDA_INIT 0.35550906759096927f

// ---------------- scratch (device globals; no runtime allocation) ----------------
__device__ float g_q[T_SEQ * E_DIM];
__device__ float g_k[T_SEQ * E_DIM];
__device__ float g_v[T_SEQ * E_DIM];
__device__ float g_lambda;
__device__ float g_rope[T_SEQ * 32 * 4];

__device__ __half g_xh[T_SEQ * E_DIM], g_xl[T_SEQ * E_DIM];
__device__ __half g_ah[T_SEQ * E_DIM], g_al[T_SEQ * E_DIM];
__device__ __half g_qbh[T_SEQ * E_DIM], g_qbl[T_SEQ * E_DIM];
__device__ __half g_kbh[T_SEQ * E_DIM];
__device__ __half g_vbh[T_SEQ * E_DIM];
__device__ __half g_wqh[E_DIM * E_DIM];
__device__ __half g_wkh[E_DIM * E_DIM];
__device__ __half g_wvh[E_DIM * E_DIM];
__device__ __half g_woh[E_DIM * E_DIM];

// ---------------- warp-MMA helpers (baseline PTX, works at sm_103 non-a) ----------------
__device__ __forceinline__ uint32_t smem_u32(const void* p) {
    uint32_t a;
    asm("{ .reg .u64 t; cvta.to.shared.u64 t, %1; cvt.u32.u64 %0, t; }" : "=r"(a) : "l"(p));
    return a;
}
__device__ __forceinline__ void ldsm4(uint32_t* r, uint32_t addr) {
    asm volatile("ldmatrix.sync.aligned.m8n8.x4.shared.b16 {%0,%1,%2,%3}, [%4];"
                 : "=r"(r[0]), "=r"(r[1]), "=r"(r[2]), "=r"(r[3]) : "r"(addr));
}
__device__ __forceinline__ void ldsm4t(uint32_t* r, uint32_t addr) {
    asm volatile("ldmatrix.sync.aligned.m8n8.x4.trans.shared.b16 {%0,%1,%2,%3}, [%4];"
                 : "=r"(r[0]), "=r"(r[1]), "=r"(r[2]), "=r"(r[3]) : "r"(addr));
}
// f16 inputs, f32 accumulate
__device__ __forceinline__ void mma16816(float* d, const uint32_t* a, const uint32_t* b) {
    asm volatile("mma.sync.aligned.m16n8k16.row.col.f32.f16.f16.f32 "
                 "{%0,%1,%2,%3}, {%4,%5,%6,%7}, {%8,%9}, {%0,%1,%2,%3};"
                 : "+f"(d[0]), "+f"(d[1]), "+f"(d[2]), "+f"(d[3])
                 : "r"(a[0]), "r"(a[1]), "r"(a[2]), "r"(a[3]), "r"(b[0]), "r"(b[1]));
}
__device__ __forceinline__ void cpa16(uint32_t s, const void* g) {
    asm volatile("cp.async.ca.shared.global [%0], [%1], 16;" :: "r"(s), "l"(g));
}
#define CPA_COMMIT() asm volatile("cp.async.commit_group;" ::: "memory")
#define CPA_WAIT(n)  asm volatile("cp.async.wait_group %0;" :: "n"(n) : "memory")

// ---------------- split-fp16 conversion ----------------
__global__ void cvt_split(const float* __restrict__ in, __half* __restrict__ hi,
                          __half* __restrict__ lo, int n) {
    int i = blockIdx.x * 256 + threadIdx.x;
    if (i < n) {
        float v = in[i];
        __half h = __float2half(v);
        hi[i] = h;
        lo[i] = __float2half(v - __half2float(h));
    }
}
__global__ void cvt_single(const float* __restrict__ in, __half* __restrict__ hi, int n) {
    int i = blockIdx.x * 256 + threadIdx.x;
    if (i < n) hi[i] = __float2half(in[i]);
}

// fused cvt for 4 weight matrices -> hi only (2-term GEMM never reads W-lo)
__global__ void cvt_weights(const float* __restrict__ Wq, const float* __restrict__ Wk,
                            const float* __restrict__ Wv, const float* __restrict__ Wo,
                            __half* __restrict__ qh, __half* __restrict__ kh,
                            __half* __restrict__ vh, __half* __restrict__ oh) {
    int i = blockIdx.x * 256 + threadIdx.x;
    int w = blockIdx.y;
    const float* src = (w == 0) ? Wq : (w == 1) ? Wk : (w == 2) ? Wv : Wo;
    __half* hi = (w == 0) ? qh : (w == 1) ? kh : (w == 2) ? vh : oh;
    hi[i] = __float2half(src[i]);
}

// ---------------- HMMA GEMM (cp.async double-buffered, 2-term): C = A * B^T ----------------
// C = (Ah + Al) * Bh^T. CTA 128x128, 8 warps (4M x 2N), K-chunk 32. blockIdx.z selects (B, C).
#define GSROW 40
#define GARR 10240
#define GBUFB 30720
#define GEMM_SMEM 61440

__global__ __launch_bounds__(256) void gemm_hmma(
    const __half* __restrict__ Ah, const __half* __restrict__ Al,
    const __half* __restrict__ B0h, const __half* __restrict__ B1h,
    const __half* __restrict__ B2h,
    float* __restrict__ C0, float* __restrict__ C1, float* __restrict__ C2,
    int M, int N, int K) {
    extern __shared__ char dsm[];
    const uint32_t sb = smem_u32(dsm);

    const int tid = threadIdx.x;
    const int lane = tid & 31, wid = tid >> 5;
    const int wm = wid & 3, wn = wid >> 2;
    const int m0 = blockIdx.y * 128, n0 = blockIdx.x * 128;
    const int z = blockIdx.z;
    const __half* Bh = (z == 0) ? B0h : (z == 1) ? B1h : B2h;
    float* C = (z == 0) ? C0 : (z == 1) ? C1 : C2;

    float acc[2][8][4];
#pragma unroll
    for (int mt = 0; mt < 2; mt++)
#pragma unroll
        for (int nt = 0; nt < 8; nt++)
#pragma unroll
            for (int i = 0; i < 4; i++) acc[mt][nt][i] = 0.f;

    int rowA[2], qA[2];
#pragma unroll
    for (int j = 0; j < 2; j++) {
        int u = tid + j * 256;
        rowA[j] = u >> 2;
        qA[j] = u & 3;
    }

    const int nchunk = K >> 5;

    auto load_chunk = [&](int c, int b) {
        int k0 = c << 5;
        uint32_t bs = sb + b * GBUFB;
#pragma unroll
        for (int j = 0; j < 2; j++) {
            uint32_t so = (uint32_t)(rowA[j] * GSROW + qA[j] * 8) * 2;
            size_t ga = (size_t)(m0 + rowA[j]) * K + k0 + qA[j] * 8;
            size_t gb = (size_t)(n0 + rowA[j]) * K + k0 + qA[j] * 8;
            cpa16(bs + so, &Ah[ga]);
            cpa16(bs + GARR + so, &Al[ga]);
            cpa16(bs + 2 * GARR + so, &Bh[gb]);
        }
        CPA_COMMIT();
    };

    load_chunk(0, 0);
    load_chunk(1, 1);

    const int quarter = lane >> 3, wi = lane & 7;

    for (int c = 0; c < nchunk; c++) {
        const int buf = c & 1;
        if (c + 1 < nchunk) CPA_WAIT(1); else CPA_WAIT(0);
        __syncthreads();

        const uint32_t uAh = sb + buf * GBUFB;
        const uint32_t uAl = uAh + GARR;
        const uint32_t uBh = uAh + 2 * GARR;

#pragma unroll
        for (int ks = 0; ks < 2; ks++) {
            uint32_t aH[2][4], aL[2][4], bH[16];
#pragma unroll
            for (int mt = 0; mt < 2; mt++) {
                uint32_t off = (uint32_t)(wm * 32 + mt * 16 + (lane & 15)) * (GSROW * 2)
                               + ks * 32 + ((lane >> 4) * 16);
                ldsm4(aH[mt], uAh + off);
                ldsm4(aL[mt], uAl + off);
            }
#pragma unroll
            for (int p = 0; p < 4; p++) {
                uint32_t off = (uint32_t)(wn * 64 + p * 16 + (quarter >> 1) * 8 + wi) * (GSROW * 2)
                               + ks * 32 + ((quarter & 1) * 16);
                ldsm4(&bH[p * 4], uBh + off);
            }
#pragma unroll
            for (int mt = 0; mt < 2; mt++)
#pragma unroll
                for (int nt = 0; nt < 8; nt++) {
                    mma16816(acc[mt][nt], aH[mt], &bH[nt * 2]);
                    mma16816(acc[mt][nt], aL[mt], &bH[nt * 2]);
                }
        }
        __syncthreads();
        if (c + 2 < nchunk) load_chunk(c + 2, buf);
    }

#pragma unroll
    for (int mt = 0; mt < 2; mt++) {
        int row = m0 + wm * 32 + mt * 16 + (lane >> 2);
#pragma unroll
        for (int nt = 0; nt < 8; nt++) {
            int col = n0 + wn * 64 + nt * 8 + (lane & 3) * 2;
            float2 v0 = make_float2(acc[mt][nt][0], acc[mt][nt][1]);
            float2 v1 = make_float2(acc[mt][nt][2], acc[mt][nt][3]);
            *(float2*)&C[(size_t)row * N + col] = v0;
            *(float2*)&C[(size_t)(row + 8) * N + col] = v1;
        }
    }
}

// ---------------- RoPE tables (tiny fp64 kernel) ----------------
__global__ void rope_tables(float* __restrict__ tab) {
    int t = blockIdx.x;
    int i = threadIdx.x;
    double inv = pow(10000.0, -(double)i / 32.0);
    double f = fmod((double)t * inv, 6.283185307179586);
    float cf = (float)cos(f), sf = (float)sin(f);
    float power = ((float)t - 1024.0f) / 512.0f;
    int je = (2 * i) & 31, jo = (2 * i + 1) & 31;
    float sv_e = (2.0f * je + 25.6f) / 89.6f;
    float sv_o = (2.0f * jo + 25.6f) / 89.6f;
    float se = powf(sv_e, power), so = powf(sv_o, power);
    int idx = (t * 32 + i) * 4;
    tab[idx] = cf; tab[idx + 1] = sf; tab[idx + 2] = se; tab[idx + 3] = so;
}

// ---------------- RoPE apply: fp32 in -> Q split fp16, K single fp16 ----------------
__global__ void rope_apply(const float* __restrict__ q, const float* __restrict__ k,
                           const float* __restrict__ tab,
                           __half* __restrict__ qh, __half* __restrict__ ql,
                           __half* __restrict__ kh) {
    int t = blockIdx.x;
    int p = threadIdx.x;
    int head = p >> 5;
    int i = p & 31;
    float4 tv = *(const float4*)&tab[(t * 32 + i) * 4];
    float cf = tv.x, sf = tv.y, se = tv.z, so = tv.w;

    size_t base = (size_t)t * E_DIM + head * 64 + 2 * i;
    float a = q[base], b = q[base + 1];
    float qa = (a * cf - b * sf) * se * 0.125f;
    float qb = (b * cf + a * sf) * so * 0.125f;
    float ka = k[base], kb = k[base + 1];
    float k0 = (ka * cf - kb * sf) / se;
    float k1 = (kb * cf + ka * sf) / so;

    __half2 v, vr;
    v.x = __float2half(qa); v.y = __float2half(qb);
    *(__half2*)&qh[base] = v;
    vr.x = __float2half(qa - __half2float(v.x));
    vr.y = __float2half(qb - __half2float(v.y));
    *(__half2*)&ql[base] = vr;
    v.x = __float2half(k0); v.y = __float2half(k1);
    *(__half2*)&kh[base] = v;
}

// ---------------- lambda scalar ----------------
__global__ void lambda_kernel(const float* __restrict__ lq1, const float* __restrict__ lk1,
                              const float* __restrict__ lq2, const float* __restrict__ lk2) {
    __shared__ float s1[64], s2[64];
    int t = threadIdx.x;
    s1[t] = lq1[t] * lk1[t];
    s2[t] = lq2[t] * lk2[t];
    __syncthreads();
    if (t == 0) {
        float a = 0.f, b = 0.f;
        for (int j = 0; j < 64; j++) { a += s1[j]; b += s2[j]; }
        g_lambda = expf(a) - expf(b) + LAMBDA_INIT;
    }
}

// ---------------- HMMA differential flash attention (fp16; Q 2-term, K/V single) ----------------
// Smem: Qh [2st][64][144B] @0, Ql @18432, Kh @36864, Vh [64][272B] @55296
#define OQH 0
#define OQL 18432
#define OKH 36864
#define OVH 55296
#define ATT_SMEM 72704

__global__ __launch_bounds__(256) void diff_attn_mma(
    const __half* __restrict__ qh, const __half* __restrict__ ql,
    const __half* __restrict__ kh,
    const __half* __restrict__ vh,
    __half* __restrict__ oh, __half* __restrict__ ol) {
    extern __shared__ char sm[];
    const uint32_t sb = smem_u32(sm);
    const int tid = threadIdx.x;
    const int lane = tid & 31, wid = tid >> 5;
    const int wm = wid & 3, st = wid >> 2;
    const int h = blockIdx.y;
    const int q0 = blockIdx.x * 64;

    // ---- load Q (both streams, hi/lo): 2048 uint4 ----
#pragma unroll
    for (int j = 0; j < 8; j++) {
        int u = tid + j * 256;
        int arr = u >> 10, rem = u & 1023;
        int qst = rem >> 9, r2 = (rem >> 3) & 63, qq = rem & 7;
        const __half* src = arr ? ql : qh;
        uint32_t off = (arr ? OQL : OQH) + (uint32_t)(qst * 64 + r2) * 144 + qq * 16;
        *(uint4*)(sm + off) =
            *(const uint4*)&src[(size_t)(q0 + r2) * E_DIM + (2 * h + qst) * 64 + qq * 8];
    }

    float O[16][4];
#pragma unroll
    for (int ct = 0; ct < 16; ct++)
#pragma unroll
        for (int i = 0; i < 4; i++) O[ct][i] = 0.f;
    float m0 = -INFINITY, m1 = -INFINITY, l0 = 0.f, l1 = 0.f;

    const int quarter = lane >> 3, wi = lane & 7;
    const uint32_t aoff_base = (uint32_t)(st * 64 + wm * 16 + (lane & 15)) * 144 + ((lane >> 4) * 16);
    const uint32_t voff_base = (uint32_t)((lane & 7) + ((lane & 8) ? 8 : 0)) * 272 + ((lane & 16) ? 16 : 0);

    for (int sbk = 0; sbk < 32; sbk++) {
        const int s0 = sbk * 64;
        __syncthreads();
        // ---- K hi: 1024 uint4 ----
#pragma unroll
        for (int j = 0; j < 4; j++) {
            int u = tid + j * 256;
            int kst = u >> 9, r2 = (u >> 3) & 63, qq = u & 7;
            uint32_t off = OKH + (uint32_t)(kst * 64 + r2) * 144 + qq * 16;
            *(uint4*)(sm + off) =
                *(const uint4*)&kh[(size_t)(s0 + r2) * E_DIM + (2 * h + kst) * 64 + qq * 8];
        }
        // ---- V single: 1024 uint4 ----
#pragma unroll
        for (int j = 0; j < 4; j++) {
            int u = tid + j * 256;
            int r2 = u >> 4, qq = u & 15;
            uint32_t off = OVH + (uint32_t)r2 * 272 + qq * 16;
            *(uint4*)(sm + off) =
                *(const uint4*)&vh[(size_t)(s0 + r2) * E_DIM + h * 128 + qq * 8];
        }
        __syncthreads();

        // ---- S = Q_st * K_st^T (Q 2-term split, K single) ----
        float sacc[8][4];
#pragma unroll
        for (int t = 0; t < 8; t++)
#pragma unroll
            for (int i = 0; i < 4; i++) sacc[t][i] = 0.f;

#pragma unroll
        for (int ks = 0; ks < 4; ks++) {
            uint32_t aQh[4], aQl[4];
            uint32_t ao = aoff_base + ks * 32;
            ldsm4(aQh, sb + OQH + ao);
            ldsm4(aQl, sb + OQL + ao);
#pragma unroll
            for (int p = 0; p < 4; p++) {
                uint32_t bo = (uint32_t)(st * 64 + p * 16 + (quarter >> 1) * 8 + wi) * 144
                              + ks * 32 + ((quarter & 1) * 16);
                uint32_t bh[4];
                ldsm4(bh, sb + OKH + bo);
                mma16816(sacc[2 * p], aQh, &bh[0]);
                mma16816(sacc[2 * p + 1], aQh, &bh[2]);
                mma16816(sacc[2 * p], aQl, &bh[0]);
                mma16816(sacc[2 * p + 1], aQl, &bh[2]);
            }
        }

        // ---- online softmax ----
        float mx0 = -INFINITY, mx1 = -INFINITY;
#pragma unroll
        for (int t = 0; t < 8; t++) {
            mx0 = fmaxf(mx0, fmaxf(sacc[t][0], sacc[t][1]));
            mx1 = fmaxf(mx1, fmaxf(sacc[t][2], sacc[t][3]));
        }
        mx0 = fmaxf(mx0, __shfl_xor_sync(0xffffffffu, mx0, 1));
        mx0 = fmaxf(mx0, __shfl_xor_sync(0xffffffffu, mx0, 2));
        mx1 = fmaxf(mx1, __shfl_xor_sync(0xffffffffu, mx1, 1));
        mx1 = fmaxf(mx1, __shfl_xor_sync(0xffffffffu, mx1, 2));
        float mn0 = fmaxf(m0, mx0), mn1 = fmaxf(m1, mx1);
        float al0 = __expf(m0 - mn0), al1 = __expf(m1 - mn1);
        m0 = mn0; m1 = mn1;

        uint32_t aPh[4][4], aPl[4][4];
        float rs0 = 0.f, rs1 = 0.f;
#pragma unroll
        for (int t = 0; t < 8; t++) {
            float p0 = __expf(sacc[t][0] - mn0);
            float p1 = __expf(sacc[t][1] - mn0);
            float p2 = __expf(sacc[t][2] - mn1);
            float p3 = __expf(sacc[t][3] - mn1);
            rs0 += p0 + p1; rs1 += p2 + p3;
            int j = t >> 1, hf = t & 1;
            __half2 hv, lv;
            hv.x = __float2half(p0); hv.y = __float2half(p1);
            lv.x = __float2half(p0 - __half2float(hv.x));
            lv.y = __float2half(p1 - __half2float(hv.y));
            aPh[j][hf * 2] = *(uint32_t*)&hv;
            aPl[j][hf * 2] = *(uint32_t*)&lv;
            hv.x = __float2half(p2); hv.y = __float2half(p3);
            lv.x = __float2half(p2 - __half2float(hv.x));
            lv.y = __float2half(p3 - __half2float(hv.y));
            aPh[j][hf * 2 + 1] = *(uint32_t*)&hv;
            aPl[j][hf * 2 + 1] = *(uint32_t*)&lv;
        }
        rs0 += __shfl_xor_sync(0xffffffffu, rs0, 1);
        rs0 += __shfl_xor_sync(0xffffffffu, rs0, 2);
        rs1 += __shfl_xor_sync(0xffffffffu, rs1, 1);
        rs1 += __shfl_xor_sync(0xffffffffu, rs1, 2);
        l0 = l0 * al0 + rs0;
        l1 = l1 * al1 + rs1;
#pragma unroll
        for (int ct = 0; ct < 16; ct++) {
            O[ct][0] *= al0; O[ct][1] *= al0;
            O[ct][2] *= al1; O[ct][3] *= al1;
        }

        // ---- O += P * V (P 2-term split, V single) ----
#pragma unroll
        for (int p8 = 0; p8 < 8; p8++) {
#pragma unroll
            for (int j = 0; j < 4; j++) {
                uint32_t vo = voff_base + (uint32_t)(j * 16) * 272 + p8 * 32;
                uint32_t bh[4];
                ldsm4t(bh, sb + OVH + vo);
                mma16816(O[2 * p8], aPh[j], &bh[0]);
                mma16816(O[2 * p8 + 1], aPh[j], &bh[2]);
                mma16816(O[2 * p8], aPl[j], &bh[0]);
                mma16816(O[2 * p8 + 1], aPl[j], &bh[2]);
            }
        }
    }

    // ---- epilogue: normalize, diff, RMS, split-fp16 out ----
    __syncthreads();
    {
        float* buf = (float*)(sm + (st ? 36864 : 0));
        float inv0 = 1.0f / l0, inv1 = 1.0f / l1;
        int r = wm * 16 + (lane >> 2);
#pragma unroll
        for (int ct = 0; ct < 16; ct++) {
            int c = ct * 8 + 2 * (lane & 3);
            *(float2*)&buf[r * 128 + c] = make_float2(O[ct][0] * inv0, O[ct][1] * inv0);
            *(float2*)&buf[(r + 8) * 128 + c] = make_float2(O[ct][2] * inv1, O[ct][3] * inv1);
        }
    }
    __syncthreads();
    {
        const float lam = g_lambda;
        const float* b0 = (const float*)sm;
        const float* b1 = (const float*)(sm + 36864);
        int r = tid >> 2, qt = tid & 3;
        float vals[32];
        float ss = 0.f;
#pragma unroll
        for (int i = 0; i < 32; i++) {
            int c = qt * 32 + i;
            float d = b0[r * 128 + c] - lam * b1[r * 128 + c];
            vals[i] = d;
            ss += d * d;
        }
        ss += __shfl_xor_sync(0xffffffffu, ss, 1);
        ss += __shfl_xor_sync(0xffffffffu, ss, 2);
        float g = rsqrtf(ss * (1.0f / 128.0f) + 1e-5f) * (1.0f - LAMBDA_INIT);
        size_t base = (size_t)(q0 + r) * E_DIM + h * 128 + qt * 32;
#pragma unroll
        for (int i = 0; i < 32; i += 2) {
            float o0 = vals[i] * g, o1 = vals[i + 1] * g;
            __half2 hv, lv;
            hv.x = __float2half(o0); hv.y = __float2half(o1);
            lv.x = __float2half(o0 - __half2float(hv.x));
            lv.y = __float2half(o1 - __half2float(hv.y));
            *(__half2*)&oh[base + i] = hv;
            *(__half2*)&ol[base + i] = lv;
        }
    }
}

// ---------------- launch ----------------
extern "C" void kernel_launch(void* const* d_in, const int* in_sizes, int n_in,
                              void* d_out, int out_size) {
    const float* x   = (const float*)d_in[0];
    const float* Wq  = (const float*)d_in[1];
    const float* Wk  = (const float*)d_in[2];
    const float* Wv  = (const float*)d_in[3];
    const float* Wo  = (const float*)d_in[4];
    const float* lq1 = (const float*)d_in[5];
    const float* lk1 = (const float*)d_in[6];
    const float* lq2 = (const float*)d_in[7];
    const float* lk2 = (const float*)d_in[8];
    float* out = (float*)d_out;

    float *pq, *pk, *pv, *ptab;
    cudaGetSymbolAddress((void**)&pq, g_q);
    cudaGetSymbolAddress((void**)&pk, g_k);
    cudaGetSymbolAddress((void**)&pv, g_v);
    cudaGetSymbolAddress((void**)&ptab, g_rope);

    __half *xh, *xl, *ah, *al, *qbh, *qbl, *kbh, *vbh;
    __half *wqh, *wkh, *wvh, *woh;
    cudaGetSymbolAddress((void**)&xh, g_xh);   cudaGetSymbolAddress((void**)&xl, g_xl);
    cudaGetSymbolAddress((void**)&ah, g_ah);   cudaGetSymbolAddress((void**)&al, g_al);
    cudaGetSymbolAddress((void**)&qbh, g_qbh); cudaGetSymbolAddress((void**)&qbl, g_qbl);
    cudaGetSymbolAddress((void**)&kbh, g_kbh);
    cudaGetSymbolAddress((void**)&vbh, g_vbh);
    cudaGetSymbolAddress((void**)&wqh, g_wqh);
    cudaGetSymbolAddress((void**)&wkh, g_wkh);
    cudaGetSymbolAddress((void**)&wvh, g_wvh);
    cudaGetSymbolAddress((void**)&woh, g_woh);

    cudaFuncSetAttribute(gemm_hmma, cudaFuncAttributeMaxDynamicSharedMemorySize, GEMM_SMEM);
    cudaFuncSetAttribute(diff_attn_mma, cudaFuncAttributeMaxDynamicSharedMemorySize, ATT_SMEM);

    const int nX = T_SEQ * E_DIM;
    const int nW = E_DIM * E_DIM;
    cvt_split<<<(nX + 255) / 256, 256>>>(x, xh, xl, nX);
    cvt_weights<<<dim3(nW / 256, 4), 256>>>(Wq, Wk, Wv, Wo, wqh, wkh, wvh, woh);

    rope_tables<<<T_SEQ, 32>>>(ptab);
    lambda_kernel<<<1, 64>>>(lq1, lk1, lq2, lk2);

    // fused Q/K/V projections, all 2-term
    gemm_hmma<<<dim3(E_DIM / 128, T_SEQ / 128, 3), 256, GEMM_SMEM>>>(
        xh, xl, wqh, wkh, wvh, pq, pk, pv, T_SEQ, E_DIM, E_DIM);

    rope_apply<<<T_SEQ, 512>>>(pq, pk, ptab, qbh, qbl, kbh);
    cvt_single<<<(nX + 255) / 256, 256>>>(pv, vbh, nX);

    diff_attn_mma<<<dim3(T_SEQ / 64, NH), 256, ATT_SMEM>>>(qbh, qbl, kbh, vbh, ah, al);

    // output projection: 2-term
    gemm_hmma<<<dim3(E_DIM / 128, T_SEQ / 128, 1), 256, GEMM_SMEM>>>(
        ah, al, woh, woh, woh, out, out, out, T_SEQ, E_DIM, E_DIM);
}